// round 3
// baseline (speedup 1.0000x reference)
#include <cuda_runtime.h>
#include <cuda_fp16.h>
#include <math.h>

// Problem constants
#define BB 128
#define SS 256
#define TT 256
#define VV 512
#define EE 256
#define HH 512
#define H2 1024
#define H4 2048

#define NBLK 128   // persistent grid size (<= #SMs, guaranteed co-resident)

// ---------------- static device scratch ----------------
__device__ float g_xs[SS * BB * EE];          // encoder embedded inputs [S,B,E]
__device__ float g_dece[TT * BB * EE];        // decoder embedded inputs [T,B,E]
__device__ float g_xproj[2 * SS * BB * H4];   // per-layer x-projection [dir,S,B,4H]
__device__ float g_y0[SS * BB * H2];          // encoder layer0 outputs [S,B,2H]
__device__ float g_enc_bsh[BB * SS * H2];     // encoder output [B,S,2H] fp32
__device__ __half g_enc16[BB * SS * H2];      // encoder output [B,S,2H] fp16
__device__ __half g_encP[BB * HH * SS];       // projected enc (enc@Wq) [B,H,S] fp16
__device__ float g_sbias[BB * SS];            // enc . bq
__device__ float g_wqT[HH * H2];              // Wq transposed [H,2H]
__device__ float g_eproj[TT * BB * H4];       // decoder e-projection [T,B,4H]
__device__ float g_d1a[TT * BB * HH];         // all decoder top hiddens [T,B,H]
__device__ float g_h0p[2][2 * BB * HH];       // enc layer0 h ping-pong
__device__ float g_c0[2 * BB * HH];
__device__ float g_h1p[2][2 * BB * HH];
__device__ float g_c1[2 * BB * HH];
__device__ float g_d0h[2][BB * HH];
__device__ float g_d0c[BB * HH];
__device__ float g_d1h[2][BB * HH];
__device__ float g_d1c[BB * HH];
__device__ float g_ctx[BB * H2];

// ---------------- software grid barrier (grid <= #SMs) ----------------
__device__ unsigned g_bar_cnt = 0;
__device__ unsigned g_bar_gen = 0;

__device__ __forceinline__ void grid_barrier(unsigned nb)
{
    __syncthreads();
    if (threadIdx.x == 0) {
        volatile unsigned* vgen = &g_bar_gen;
        unsigned gen = *vgen;
        __threadfence();
        unsigned arr = atomicAdd(&g_bar_cnt, 1u);
        if (arr == nb - 1) {
            atomicExch(&g_bar_cnt, 0u);
            __threadfence();
            atomicAdd(&g_bar_gen, 1u);          // release
        } else {
            while (*vgen == gen) { __nanosleep(32); }
            __threadfence();
        }
    }
    __syncthreads();
}

// ---------------- embedding gather ----------------
__global__ __launch_bounds__(256) void gather_kernel(
    const int* __restrict__ tok, const float* __restrict__ emb,
    float* __restrict__ out, int Slen)
{
    long i = (long)blockIdx.x * 256 + threadIdx.x;
    long total = (long)Slen * BB * EE;
    if (i >= total) return;
    int e = (int)(i % EE);
    long r = i / EE;
    int b = (int)(r % BB);
    int t = (int)(r / BB);
    int tk = tok[(long)b * Slen + t];
    out[i] = (tk == 0) ? 0.f : emb[(long)tk * EE + e];
}

// ---------------- Wq transpose ----------------
__global__ __launch_bounds__(256) void transpose_wq_kernel(
    const float* __restrict__ Wq, float* __restrict__ WqT)
{
    int i = blockIdx.x * 256 + threadIdx.x;
    if (i < HH * H2) {
        int h = i / H2, j = i % H2;
        WqT[i] = Wq[(size_t)j * HH + h];
    }
}

// ---------------- sbias[b,s] = enc[b,s,:] . bq ----------------
__global__ __launch_bounds__(256) void sbias_kernel(
    const float* __restrict__ enc, const float* __restrict__ bq,
    float* __restrict__ sbias)
{
    int bi = blockIdx.x;                // 0..4095
    int b = bi >> 5, s0 = (bi & 31) * 8;
    int w = threadIdx.x >> 5, lane = threadIdx.x & 31;
    int s = s0 + w;
    const float* e = enc + ((size_t)b * SS + s) * H2;
    float acc = 0.f;
#pragma unroll 8
    for (int k = lane; k < H2; k += 32) acc += e[k] * bq[k];
#pragma unroll
    for (int o = 16; o; o >>= 1) acc += __shfl_xor_sync(0xffffffffu, acc, o);
    if (lane == 0) sbias[(size_t)b * SS + s] = acc;
}

// ---------------- big SGEMM: C[m,n] = sum_k A[m,k]*W[n,k] (+b1+b2) ----------------
// BM=BN=128, BK=16, 256 threads, 8x8/thread, k-major smem with LDS.128 reads.
// cmode 0: C[m*ldc+n]
// cmode 1: m = t*128+b -> C[b*T*V + t*V + n]          (logits)
// cmode 2: m = b*256+s -> Ch[b*H*S + n*S + s] (fp16)  (encP transpose)
__global__ __launch_bounds__(256) void sgemm_bias_kernel(
    const float* __restrict__ A, int lda,
    const float* __restrict__ W, int ldw,
    const float* __restrict__ b1, const float* __restrict__ b2,
    float* __restrict__ C, int ldc, int K, int cmode, __half* __restrict__ Ch)
{
    __shared__ float As[16][132];
    __shared__ float Bs[16][132];
    int tid = threadIdx.x;
    int tx = tid & 15, ty = tid >> 4;
    int m0 = blockIdx.x * 128, n0 = blockIdx.y * 128;

    float acc[8][8];
#pragma unroll
    for (int i = 0; i < 8; i++)
#pragma unroll
        for (int j = 0; j < 8; j++) acc[i][j] = 0.f;

    int lrow = tid >> 1;
    int lk0 = (tid & 1) * 8;

    for (int k0 = 0; k0 < K; k0 += 16) {
        {
            const float4* ap = (const float4*)(A + (size_t)(m0 + lrow) * lda + k0 + lk0);
            float4 v0 = ap[0], v1 = ap[1];
            As[lk0 + 0][lrow] = v0.x; As[lk0 + 1][lrow] = v0.y;
            As[lk0 + 2][lrow] = v0.z; As[lk0 + 3][lrow] = v0.w;
            As[lk0 + 4][lrow] = v1.x; As[lk0 + 5][lrow] = v1.y;
            As[lk0 + 6][lrow] = v1.z; As[lk0 + 7][lrow] = v1.w;
        }
        {
            const float4* wp = (const float4*)(W + (size_t)(n0 + lrow) * ldw + k0 + lk0);
            float4 v0 = wp[0], v1 = wp[1];
            Bs[lk0 + 0][lrow] = v0.x; Bs[lk0 + 1][lrow] = v0.y;
            Bs[lk0 + 2][lrow] = v0.z; Bs[lk0 + 3][lrow] = v0.w;
            Bs[lk0 + 4][lrow] = v1.x; Bs[lk0 + 5][lrow] = v1.y;
            Bs[lk0 + 6][lrow] = v1.z; Bs[lk0 + 7][lrow] = v1.w;
        }
        __syncthreads();
#pragma unroll
        for (int kk = 0; kk < 16; kk++) {
            float4 a0 = *(const float4*)&As[kk][ty * 8];
            float4 a1 = *(const float4*)&As[kk][ty * 8 + 4];
            float4 w0 = *(const float4*)&Bs[kk][tx * 8];
            float4 w1 = *(const float4*)&Bs[kk][tx * 8 + 4];
            float a[8] = {a0.x, a0.y, a0.z, a0.w, a1.x, a1.y, a1.z, a1.w};
            float w[8] = {w0.x, w0.y, w0.z, w0.w, w1.x, w1.y, w1.z, w1.w};
#pragma unroll
            for (int i = 0; i < 8; i++)
#pragma unroll
                for (int j = 0; j < 8; j++) acc[i][j] += a[i] * w[j];
        }
        __syncthreads();
    }

#pragma unroll
    for (int i = 0; i < 8; i++) {
        int m = m0 + ty * 8 + i;
#pragma unroll
        for (int j = 0; j < 8; j++) {
            int n = n0 + tx * 8 + j;
            float v = acc[i][j];
            if (b1) v += b1[n];
            if (b2) v += b2[n];
            if (cmode == 0) {
                C[(size_t)m * ldc + n] = v;
            } else if (cmode == 1) {
                int t = m >> 7, b = m & 127;
                C[((size_t)b * TT + t) * VV + n] = v;
            } else {
                int b = m >> 8, s = m & 255;
                Ch[((size_t)b * HH + n) * SS + s] = __float2half(v);
            }
        }
    }
}

// ---------------- persistent encoder layer (both dirs, all S steps) ----------------
__global__ __launch_bounds__(256) void enc_layer_kernel(
    const float* __restrict__ xproj, const float* __restrict__ Whh,
    float* __restrict__ hA, float* __restrict__ hB, float* __restrict__ c_buf,
    float* __restrict__ ya, __half* __restrict__ y16, int ymode)
{
    int bx = blockIdx.x;
    int mt = bx & 7, ht = bx >> 3;
    int m0 = mt * 32;
    int dir = m0 >> 7;
    int b0 = m0 & 127;
    int h0 = ht * 32;
    int tid = threadIdx.x;
    int tc = tid & 31, tr = tid >> 5;

    __shared__ float As[32][33];
    __shared__ float Ws[4][32][33];

    const float* Wbase = Whh + (size_t)dir * H4 * HH;
    float* hin = hA;
    float* hout = hB;

    for (int step = 0; step < SS; step++) {
        int t = dir ? (SS - 1 - step) : step;
        const float* Aptr = hin + (size_t)dir * BB * HH + (size_t)b0 * HH;

        float acc[4][4];
#pragma unroll
        for (int i = 0; i < 4; i++)
#pragma unroll
            for (int g = 0; g < 4; g++) acc[i][g] = 0.f;

        for (int k0 = 0; k0 < HH; k0 += 32) {
#pragma unroll
            for (int l = 0; l < 4; l++) {
                int lin = tid + l * 256;
                int mm = lin >> 5, kk = lin & 31;
                As[kk][mm] = Aptr[(size_t)mm * HH + k0 + kk];
            }
#pragma unroll
            for (int l = 0; l < 16; l++) {
                int lin = tid + l * 256;
                int g = lin >> 10;
                int rem = lin & 1023;
                int j = rem >> 5, kk = rem & 31;
                Ws[g][j][kk] = Wbase[(size_t)(g * HH + h0 + j) * HH + k0 + kk];
            }
            __syncthreads();
#pragma unroll
            for (int kk = 0; kk < 32; kk++) {
                float a0 = As[kk][tr * 4 + 0];
                float a1 = As[kk][tr * 4 + 1];
                float a2 = As[kk][tr * 4 + 2];
                float a3 = As[kk][tr * 4 + 3];
                float w0 = Ws[0][tc][kk], w1 = Ws[1][tc][kk];
                float w2 = Ws[2][tc][kk], w3 = Ws[3][tc][kk];
                acc[0][0] += a0 * w0; acc[0][1] += a0 * w1; acc[0][2] += a0 * w2; acc[0][3] += a0 * w3;
                acc[1][0] += a1 * w0; acc[1][1] += a1 * w1; acc[1][2] += a1 * w2; acc[1][3] += a1 * w3;
                acc[2][0] += a2 * w0; acc[2][1] += a2 * w1; acc[2][2] += a2 * w2; acc[2][3] += a2 * w3;
                acc[3][0] += a3 * w0; acc[3][1] += a3 * w1; acc[3][2] += a3 * w2; acc[3][3] += a3 * w3;
            }
            __syncthreads();
        }

        const float* xp_base = xproj + ((size_t)dir * SS + t) * BB * H4;
#pragma unroll
        for (int i = 0; i < 4; i++) {
            int b = b0 + tr * 4 + i;
            int h = h0 + tc;
            const float* xp = xp_base + (size_t)b * H4;
            float gi = acc[i][0] + xp[h];
            float gf = acc[i][1] + xp[HH + h];
            float gg = acc[i][2] + xp[2 * HH + h];
            float go = acc[i][3] + xp[3 * HH + h];
            float ig = 1.f / (1.f + expf(-gi));
            float fg = 1.f / (1.f + expf(-gf));
            float gv = tanhf(gg);
            float og = 1.f / (1.f + expf(-go));
            size_t sidx = (size_t)dir * BB * HH + (size_t)b * HH + h;
            float c = fg * c_buf[sidx] + ig * gv;
            c_buf[sidx] = c;
            float hv = og * tanhf(c);
            hout[sidx] = hv;
            if (ymode == 0) {
                ya[((size_t)t * BB + b) * H2 + dir * HH + h] = hv;
            } else {
                size_t oi = ((size_t)b * SS + t) * H2 + dir * HH + h;
                ya[oi] = hv;
                y16[oi] = __float2half(hv);
            }
        }
        grid_barrier(NBLK);
        float* tmp = hin; hin = hout; hout = tmp;
    }
}

// ---------------- decoder cell body (device, runs on all 128 blocks) ----------------
__device__ __forceinline__ void dec_cell_phase(
    float As[32][33], float Ws[4][16][33], int bx, int tid,
    const float* Cinit, const float* b1, const float* b2,
    const float* A1, int lda1, const float* W1, int ldw1, int K1,
    const float* A2, int lda2, const float* W2, int ldw2, int K2,
    float* c_buf, float* h_out, float* extra)
{
    int m0 = (bx & 3) * 32;
    int h0 = (bx >> 2) * 16;
    int tc = tid & 15, tr = tid >> 4;

    float acc[2][4];
#pragma unroll
    for (int i = 0; i < 2; i++)
#pragma unroll
        for (int g = 0; g < 4; g++) acc[i][g] = 0.f;

    for (int seg = 0; seg < 2; seg++) {
        const float* A = seg ? A2 : A1;
        const float* W = seg ? W2 : W1;
        int lda = seg ? lda2 : lda1;
        int ldw = seg ? ldw2 : ldw1;
        int K = seg ? K2 : K1;
        for (int k0 = 0; k0 < K; k0 += 32) {
#pragma unroll
            for (int l = 0; l < 4; l++) {
                int lin = tid + l * 256;
                int mm = lin >> 5, kk = lin & 31;
                As[kk][mm] = A[(size_t)(m0 + mm) * lda + k0 + kk];
            }
#pragma unroll
            for (int l = 0; l < 8; l++) {
                int lin = tid + l * 256;
                int g = lin >> 9;
                int rem = lin & 511;
                int j = rem >> 5, kk = rem & 31;
                Ws[g][j][kk] = W[(size_t)(g * HH + h0 + j) * ldw + k0 + kk];
            }
            __syncthreads();
#pragma unroll
            for (int kk = 0; kk < 32; kk++) {
                float a0 = As[kk][tr * 2 + 0];
                float a1 = As[kk][tr * 2 + 1];
                float w0 = Ws[0][tc][kk], w1 = Ws[1][tc][kk];
                float w2 = Ws[2][tc][kk], w3 = Ws[3][tc][kk];
                acc[0][0] += a0 * w0; acc[0][1] += a0 * w1; acc[0][2] += a0 * w2; acc[0][3] += a0 * w3;
                acc[1][0] += a1 * w0; acc[1][1] += a1 * w1; acc[1][2] += a1 * w2; acc[1][3] += a1 * w3;
            }
            __syncthreads();
        }
    }

#pragma unroll
    for (int i = 0; i < 2; i++) {
        int b = m0 + tr * 2 + i;
        int h = h0 + tc;
        float gi = acc[i][0], gf = acc[i][1], gg = acc[i][2], go = acc[i][3];
        if (Cinit) {
            const float* cp = Cinit + (size_t)b * H4;
            gi += cp[h]; gf += cp[HH + h]; gg += cp[2 * HH + h]; go += cp[3 * HH + h];
        } else {
            gi += b1[h] + b2[h];
            gf += b1[HH + h] + b2[HH + h];
            gg += b1[2 * HH + h] + b2[2 * HH + h];
            go += b1[3 * HH + h] + b2[3 * HH + h];
        }
        float ig = 1.f / (1.f + expf(-gi));
        float fg = 1.f / (1.f + expf(-gf));
        float gv = tanhf(gg);
        float og = 1.f / (1.f + expf(-go));
        size_t idx = (size_t)b * HH + h;
        float c = fg * c_buf[idx] + ig * gv;
        c_buf[idx] = c;
        float hv = og * tanhf(c);
        h_out[idx] = hv;
        if (extra) extra[idx] = hv;
    }
}

// ---------------- persistent decoder (all T steps) ----------------
__global__ __launch_bounds__(256) void decoder_kernel(
    const __half* __restrict__ encP, const __half* __restrict__ enc16,
    const float* __restrict__ sbias, const int* __restrict__ source,
    const float* __restrict__ eproj,
    const float* __restrict__ dWih0, const float* __restrict__ dWhh0,
    const float* __restrict__ dWih1, const float* __restrict__ dWhh1,
    const float* __restrict__ dbih1, const float* __restrict__ dbhh1,
    float* __restrict__ d0h, float* __restrict__ d0c,
    float* __restrict__ d1h, float* __restrict__ d1c,
    float* __restrict__ ctx, float* __restrict__ d1a)
{
    int bx = blockIdx.x;
    int tid = threadIdx.x;

    __shared__ float s_As[32][33];
    __shared__ float s_Ws[4][16][33];
    __shared__ float shd[512];
    __shared__ float sred[256];
    __shared__ float sattn[256];

    for (int t = 0; t < TT; t++) {
        int cur = t & 1;
        const float* p1c = d1h + (size_t)cur * BB * HH;
        const float* p0c = d0h + (size_t)cur * BB * HH;
        float* p0n = d0h + (size_t)(cur ^ 1) * BB * HH;
        float* p1n = d1h + (size_t)(cur ^ 1) * BB * HH;

        // ---- phase 1: attention scores + softmax + context (block = batch b) ----
        {
            int b = bx;
            shd[tid] = p1c[(size_t)b * HH + tid];
            shd[tid + 256] = p1c[(size_t)b * HH + tid + 256];
            __syncthreads();

            int s = tid;
            float sc = sbias[(size_t)b * SS + s];
            const __half* ep = encP + (size_t)b * HH * SS + s;
#pragma unroll 8
            for (int h = 0; h < HH; h++) sc += __half2float(ep[(size_t)h * SS]) * shd[h];
            if (source[(size_t)b * SS + s] == 0) sc = -1e9f;

            sred[tid] = sc;
            __syncthreads();
            for (int o = 128; o; o >>= 1) {
                if (tid < o) sred[tid] = fmaxf(sred[tid], sred[tid + o]);
                __syncthreads();
            }
            float mx = sred[0];
            __syncthreads();
            float e = expf(sc - mx);
            sred[tid] = e;
            __syncthreads();
            for (int o = 128; o; o >>= 1) {
                if (tid < o) sred[tid] += sred[tid + o];
                __syncthreads();
            }
            sattn[tid] = e / sred[0];
            __syncthreads();

            // ctx: thread handles h pairs {2tid,2tid+1} and {512+2tid, 512+2tid+1}
            float a0x = 0.f, a0y = 0.f, a1x = 0.f, a1y = 0.f;
            const __half2* e2 = (const __half2*)(enc16 + (size_t)b * SS * H2);
            for (int ss = 0; ss < SS; ss++) {
                float a = sattn[ss];
                float2 f0 = __half22float2(e2[(size_t)ss * 512 + tid]);
                float2 f1 = __half22float2(e2[(size_t)ss * 512 + 256 + tid]);
                a0x += a * f0.x; a0y += a * f0.y;
                a1x += a * f1.x; a1y += a * f1.y;
            }
            float2* cp = (float2*)(ctx + (size_t)b * H2);
            cp[tid] = make_float2(a0x, a0y);
            cp[256 + tid] = make_float2(a1x, a1y);
        }
        grid_barrier(NBLK);

        // ---- phase 2: cell0 ----
        dec_cell_phase(s_As, s_Ws, bx, tid,
                       eproj + (size_t)t * BB * H4, nullptr, nullptr,
                       ctx, H2, dWih0 + EE, EE + H2, H2,
                       p0c, HH, dWhh0, HH, HH,
                       d0c, p0n, nullptr);
        grid_barrier(NBLK);

        // ---- phase 3: cell1 ----
        dec_cell_phase(s_As, s_Ws, bx, tid,
                       nullptr, dbih1, dbhh1,
                       p0n, HH, dWih1, HH, HH,
                       p1c, HH, dWhh1, HH, HH,
                       d1c, p1n, d1a + (size_t)t * BB * HH);
        grid_barrier(NBLK);
    }
}

// ---------------- sum fwd/bwd final states ----------------
__global__ __launch_bounds__(256) void sum_dirs_kernel(
    const float* __restrict__ in, float* __restrict__ out, int n)
{
    int i = blockIdx.x * 256 + threadIdx.x;
    if (i < n) out[i] = in[i] + in[n + i];
}

// =======================================================================
extern "C" void kernel_launch(void* const* d_in, const int* in_sizes, int n_in,
                              void* d_out, int out_size)
{
    const int* source = (const int*)d_in[0];
    const int* dec_in = (const int*)d_in[1];
    const float* emb = (const float*)d_in[2];
    const float* eWih0 = (const float*)d_in[3];
    const float* eWhh0 = (const float*)d_in[4];
    const float* ebih0 = (const float*)d_in[5];
    const float* ebhh0 = (const float*)d_in[6];
    const float* eWih1 = (const float*)d_in[7];
    const float* eWhh1 = (const float*)d_in[8];
    const float* ebih1 = (const float*)d_in[9];
    const float* ebhh1 = (const float*)d_in[10];
    const float* dWih0 = (const float*)d_in[11];
    const float* dWhh0 = (const float*)d_in[12];
    const float* dbih0 = (const float*)d_in[13];
    const float* dbhh0 = (const float*)d_in[14];
    const float* dWih1 = (const float*)d_in[15];
    const float* dWhh1 = (const float*)d_in[16];
    const float* dbih1 = (const float*)d_in[17];
    const float* dbhh1 = (const float*)d_in[18];
    const float* Wq = (const float*)d_in[19];
    const float* bq = (const float*)d_in[20];
    const float* Wout = (const float*)d_in[21];
    const float* bout = (const float*)d_in[22];
    float* out = (float*)d_out;

    float *p_xs, *p_dece, *p_xproj, *p_y0, *p_bsh, *p_sbias, *p_wqT, *p_eproj, *p_d1a;
    float *p_h0, *p_c0, *p_h1, *p_c1, *p_d0h, *p_d0c, *p_d1h, *p_d1c, *p_ctx;
    __half *p_enc16, *p_encP;
    cudaGetSymbolAddress((void**)&p_xs, g_xs);
    cudaGetSymbolAddress((void**)&p_dece, g_dece);
    cudaGetSymbolAddress((void**)&p_xproj, g_xproj);
    cudaGetSymbolAddress((void**)&p_y0, g_y0);
    cudaGetSymbolAddress((void**)&p_bsh, g_enc_bsh);
    cudaGetSymbolAddress((void**)&p_enc16, g_enc16);
    cudaGetSymbolAddress((void**)&p_encP, g_encP);
    cudaGetSymbolAddress((void**)&p_sbias, g_sbias);
    cudaGetSymbolAddress((void**)&p_wqT, g_wqT);
    cudaGetSymbolAddress((void**)&p_eproj, g_eproj);
    cudaGetSymbolAddress((void**)&p_d1a, g_d1a);
    cudaGetSymbolAddress((void**)&p_h0, g_h0p);
    cudaGetSymbolAddress((void**)&p_c0, g_c0);
    cudaGetSymbolAddress((void**)&p_h1, g_h1p);
    cudaGetSymbolAddress((void**)&p_c1, g_c1);
    cudaGetSymbolAddress((void**)&p_d0h, g_d0h);
    cudaGetSymbolAddress((void**)&p_d0c, g_d0c);
    cudaGetSymbolAddress((void**)&p_d1h, g_d1h);
    cudaGetSymbolAddress((void**)&p_d1c, g_d1c);
    cudaGetSymbolAddress((void**)&p_ctx, g_ctx);

    const size_t hc_bytes = (size_t)2 * BB * HH * sizeof(float);
    cudaMemsetAsync(p_h0, 0, hc_bytes);
    cudaMemsetAsync(p_c0, 0, hc_bytes);
    cudaMemsetAsync(p_h1, 0, hc_bytes);
    cudaMemsetAsync(p_c1, 0, hc_bytes);

    // gathers + Wq transpose
    {
        long total = (long)SS * BB * EE;
        gather_kernel<<<(unsigned)((total + 255) / 256), 256>>>(source, emb, p_xs, SS);
        gather_kernel<<<(unsigned)((total + 255) / 256), 256>>>(dec_in, emb, p_dece, TT);
        transpose_wq_kernel<<<(HH * H2) / 256, 256>>>(Wq, p_wqT);
    }

    const size_t slab = (size_t)SS * BB * H4;
    dim3 g_big(256, 16);   // M=32768, N=2048

    // ---- encoder layer 0 ----
    for (int d = 0; d < 2; d++) {
        sgemm_bias_kernel<<<g_big, 256>>>(
            p_xs, EE, eWih0 + (size_t)d * H4 * EE, EE,
            ebih0 + (size_t)d * H4, ebhh0 + (size_t)d * H4,
            p_xproj + d * slab, H4, EE, 0, nullptr);
    }
    enc_layer_kernel<<<NBLK, 256>>>(p_xproj, eWhh0,
                                    p_h0, p_h0 + 2 * BB * HH, p_c0,
                                    p_y0, nullptr, 0);

    // ---- encoder layer 1 ----
    for (int d = 0; d < 2; d++) {
        sgemm_bias_kernel<<<g_big, 256>>>(
            p_y0, H2, eWih1 + (size_t)d * H4 * H2, H2,
            ebih1 + (size_t)d * H4, ebhh1 + (size_t)d * H4,
            p_xproj + d * slab, H4, H2, 0, nullptr);
    }
    enc_layer_kernel<<<NBLK, 256>>>(p_xproj, eWhh1,
                                    p_h1, p_h1 + 2 * BB * HH, p_c1,
                                    p_bsh, p_enc16, 1);

    // ---- attention precompute: encP = enc @ Wq -> [B,H,S] fp16 ; sbias = enc.bq ----
    sgemm_bias_kernel<<<dim3(256, 4), 256>>>(p_bsh, H2, p_wqT, H2,
                                             nullptr, nullptr, nullptr, 0, H2, 2, p_encP);
    sbias_kernel<<<4096, 256>>>(p_bsh, bq, p_sbias);

    // ---- initial decoder states: sum directions ----
    {
        int n = BB * HH;
        sum_dirs_kernel<<<n / 256, 256>>>(p_h0, p_d0h, n);
        sum_dirs_kernel<<<n / 256, 256>>>(p_c0, p_d0c, n);
        sum_dirs_kernel<<<n / 256, 256>>>(p_h1, p_d1h, n);
        sum_dirs_kernel<<<n / 256, 256>>>(p_c1, p_d1c, n);
    }

    // ---- decoder e-projection ----
    sgemm_bias_kernel<<<g_big, 256>>>(p_dece, EE, dWih0, EE + H2,
                                      dbih0, dbhh0, p_eproj, H4, EE, 0, nullptr);

    // ---- persistent decoder ----
    decoder_kernel<<<NBLK, 256>>>(p_encP, p_enc16, p_sbias, source, p_eproj,
                                  dWih0, dWhh0, dWih1, dWhh1, dbih1, dbhh1,
                                  p_d0h, p_d0c, p_d1h, p_d1c, p_ctx, p_d1a);

    // ---- logits ----
    sgemm_bias_kernel<<<dim3(256, 4), 256>>>(p_d1a, HH, Wout, HH,
                                             bout, nullptr, out, VV, HH, 1, nullptr);
}

// round 5
// speedup vs baseline: 2.8131x; 2.8131x over previous
#include <cuda_runtime.h>
#include <cuda_fp16.h>
#include <math.h>

#define BB 128
#define SS 256
#define TT 256
#define VV 512
#define EE 256
#define HH 512
#define H2 1024
#define H4 2048
#define NBLK 128

// ---------------- scratch ----------------
__device__ __half g_xs16[SS * BB * EE];
__device__ __half g_dece16[TT * BB * EE];
__device__ float  g_xproj[2 * (size_t)SS * BB * H4];
__device__ __half g_y016[(size_t)SS * BB * H2];
__device__ __half g_enc16[(size_t)BB * SS * H2];
__device__ __half g_encP[(size_t)BB * HH * SS];
__device__ float  g_sbias[BB * SS];
__device__ float  g_eproj[(size_t)TT * BB * H4];
__device__ __half g_d1a16[(size_t)TT * BB * HH];
// fp16 weights
__device__ __half g_ewih0[2 * H4 * EE];
__device__ __half g_ewih1[2 * (size_t)H4 * H2];
__device__ __half g_ewhh0r[2 * (size_t)H4 * HH];
__device__ __half g_ewhh1r[2 * (size_t)H4 * HH];
__device__ __half g_dwihA[H4 * EE];
__device__ __half g_wc0[(size_t)H4 * 1536];
__device__ __half g_wc1[(size_t)H4 * H2];
__device__ __half g_wqT16[(size_t)HH * H2];
__device__ __half g_wout16[VV * HH];
// states
__device__ __half g_eh0p[2][2 * BB * HH];
__device__ float  g_ec0[2 * BB * HH];
__device__ __half g_eh1p[2][2 * BB * HH];
__device__ float  g_ec1[2 * BB * HH];
__device__ __half g_d0h[2][BB * HH];
__device__ float  g_d0c[BB * HH];
__device__ __half g_d1h[2][BB * HH];
__device__ float  g_d1c[BB * HH];
__device__ __half g_ctx16[BB * H2];
__device__ unsigned g_bar_cnt = 0, g_bar_gen = 0;

// ---------------- grid barrier ----------------
__device__ __forceinline__ void grid_barrier(unsigned nb)
{
    __threadfence();
    __syncthreads();
    if (threadIdx.x == 0) {
        volatile unsigned* vgen = &g_bar_gen;
        unsigned gen = *vgen;
        unsigned arr = atomicAdd(&g_bar_cnt, 1u);
        if (arr == nb - 1) {
            atomicExch(&g_bar_cnt, 0u);
            __threadfence();
            atomicAdd(&g_bar_gen, 1u);
        } else {
            while (*vgen == gen) { __nanosleep(32); }
            __threadfence();
        }
    }
    __syncthreads();
}

// ---------------- mma helpers ----------------
__device__ __forceinline__ unsigned smem_u32(const void* p)
{
    return (unsigned)__cvta_generic_to_shared(p);
}
__device__ __forceinline__ void ldmx4(unsigned a, unsigned& r0, unsigned& r1,
                                      unsigned& r2, unsigned& r3)
{
    asm volatile("ldmatrix.sync.aligned.m8n8.x4.shared.b16 {%0,%1,%2,%3}, [%4];"
                 : "=r"(r0), "=r"(r1), "=r"(r2), "=r"(r3) : "r"(a));
}
__device__ __forceinline__ void mma16816(float* d, const unsigned* a, const unsigned* b)
{
    asm volatile("mma.sync.aligned.m16n8k16.row.col.f32.f16.f16.f32 "
                 "{%0,%1,%2,%3}, {%4,%5,%6,%7}, {%8,%9}, {%0,%1,%2,%3};"
                 : "+f"(d[0]), "+f"(d[1]), "+f"(d[2]), "+f"(d[3])
                 : "r"(a[0]), "r"(a[1]), "r"(a[2]), "r"(a[3]), "r"(b[0]), "r"(b[1]));
}

// ---------------- conversion kernels ----------------
__global__ __launch_bounds__(256) void gather16_kernel(
    const int* __restrict__ tok, const float* __restrict__ emb,
    __half* __restrict__ out, int Slen)
{
    long i = (long)blockIdx.x * 256 + threadIdx.x;
    if (i >= (long)Slen * BB * EE) return;
    int e = (int)(i % EE);
    long r = i / EE;
    int b = (int)(r % BB), t = (int)(r / BB);
    int tk = tok[(long)b * Slen + t];
    out[i] = __float2half((tk == 0) ? 0.f : emb[(long)tk * EE + e]);
}

__global__ __launch_bounds__(256) void cvt_plain(const float* __restrict__ s,
                                                 __half* __restrict__ d, int n)
{
    int i = blockIdx.x * 256 + threadIdx.x;
    if (i < n) d[i] = __float2half(s[i]);
}

__global__ __launch_bounds__(256) void cvt_slice(const float* __restrict__ s, int sld,
                                                 __half* __restrict__ d, int dcols, int n)
{
    int i = blockIdx.x * 256 + threadIdx.x;
    if (i >= n) return;
    int r = i / dcols, c = i % dcols;
    d[i] = __float2half(s[(size_t)r * sld + c]);
}

__global__ __launch_bounds__(256) void cvt_wq(const float* __restrict__ Wq,
                                              __half* __restrict__ d)
{
    int i = blockIdx.x * 256 + threadIdx.x;
    if (i >= HH * H2) return;
    int h = i >> 10, j = i & 1023;
    d[i] = __float2half(Wq[(size_t)j * HH + h]);
}

// encoder Whh remap: per dir, grouped col gc=blk*32+c, blk owns h0=blk*8
__global__ __launch_bounds__(256) void cvt_enc_whh(const float* __restrict__ s,
                                                   __half* __restrict__ d)
{
    int i = blockIdx.x * 256 + threadIdx.x;
    if (i >= 2 * 2048 * 512) return;
    int dir = i >> 20, rem = i & 1048575;
    int gc = rem >> 9, k = rem & 511;
    int blk = gc >> 5, c = gc & 31;
    int tl = c >> 3, p = c & 1, j = (c & 7) >> 1;
    int gate = (tl >> 1) * 2 + p;
    int h = blk * 8 + (tl & 1) * 4 + j;
    d[i] = __float2half(s[((size_t)dir * 2048 + gate * 512 + h) * 512 + k]);
}

// decoder cell0 combined [ctx(Wih cols 256..1279) | Whh0], remap gc=blk*16+c, h0=blk*4
__global__ __launch_bounds__(256) void cvt_dec_w0(const float* __restrict__ Wih,
                                                  const float* __restrict__ Whh,
                                                  __half* __restrict__ d)
{
    int i = blockIdx.x * 256 + threadIdx.x;
    if (i >= 2048 * 1536) return;
    int gc = i / 1536, k = i % 1536;
    int blk = gc >> 4, c = gc & 15;
    int tl = c >> 3, p = c & 1, j = (c & 7) >> 1;
    int grow = (tl * 2 + p) * 512 + blk * 4 + j;
    float v = (k < 1024) ? Wih[(size_t)grow * 1280 + 256 + k]
                         : Whh[(size_t)grow * 512 + (k - 1024)];
    d[i] = __float2half(v);
}

__global__ __launch_bounds__(256) void cvt_dec_w1(const float* __restrict__ Wih,
                                                  const float* __restrict__ Whh,
                                                  __half* __restrict__ d)
{
    int i = blockIdx.x * 256 + threadIdx.x;
    if (i >= 2048 * 1024) return;
    int gc = i >> 10, k = i & 1023;
    int blk = gc >> 4, c = gc & 15;
    int tl = c >> 3, p = c & 1, j = (c & 7) >> 1;
    int grow = (tl * 2 + p) * 512 + blk * 4 + j;
    float v = (k < 512) ? Wih[(size_t)grow * 512 + k]
                        : Whh[(size_t)grow * 512 + (k - 512)];
    d[i] = __float2half(v);
}

__global__ __launch_bounds__(256) void sbias16_kernel(
    const __half* __restrict__ enc, const float* __restrict__ bq,
    float* __restrict__ sbias)
{
    int bi = blockIdx.x;
    int b = bi >> 5, s = (bi & 31) * 8 + (threadIdx.x >> 5);
    int lane = threadIdx.x & 31;
    const __half* e = enc + ((size_t)b * SS + s) * H2;
    float acc = 0.f;
#pragma unroll 8
    for (int k = lane; k < H2; k += 32) acc += __half2float(e[k]) * bq[k];
#pragma unroll
    for (int o = 16; o; o >>= 1) acc += __shfl_xor_sync(0xffffffffu, acc, o);
    if (lane == 0) sbias[(size_t)b * SS + s] = acc;
}

__global__ __launch_bounds__(256) void init_dec_kernel(
    const __half* __restrict__ eh0, const float* __restrict__ ec0,
    const __half* __restrict__ eh1, const float* __restrict__ ec1,
    __half* __restrict__ d0h, float* __restrict__ d0c,
    __half* __restrict__ d1h, float* __restrict__ d1c)
{
    int i = blockIdx.x * 256 + threadIdx.x;
    if (i >= BB * HH) return;
    d0h[i] = __float2half(__half2float(eh0[i]) + __half2float(eh0[BB * HH + i]));
    d0c[i] = ec0[i] + ec0[BB * HH + i];
    d1h[i] = __float2half(__half2float(eh1[i]) + __half2float(eh1[BB * HH + i]));
    d1c[i] = ec1[i] + ec1[BB * HH + i];
}

// ---------------- generic fp16 mma GEMM: C[m][n] = A[m][:]·W[n][:] (+b1+b2) --------
// tile 128x64, 256 thr. cmode0: C[m*ldc+n]; 1: m=t*128+b -> C[(b*T+t)*V+n];
// 2: m=b*256+s -> Ch[(b*H+n)*S+s] fp16
__global__ __launch_bounds__(256) void gemm16_kernel(
    const __half* __restrict__ A, int lda,
    const __half* __restrict__ W, int ldw,
    const float* __restrict__ b1, const float* __restrict__ b2,
    float* __restrict__ C, int ldc, __half* __restrict__ Ch, int K, int cmode)
{
    __shared__ __align__(16) __half As[128 * 72];
    __shared__ __align__(16) __half Bs[64 * 72];
    int tid = threadIdx.x, lane = tid & 31, w = tid >> 5;
    int m0 = blockIdx.x * 128, n0 = blockIdx.y * 64;
    float d[8][4];
#pragma unroll
    for (int p = 0; p < 8; p++)
#pragma unroll
        for (int k = 0; k < 4; k++) d[p][k] = 0.f;
    int arow = w * 16 + (lane & 7) + ((lane >> 3) & 1) * 8;
    int akof = (lane >> 4) * 8;
    int brow = (lane & 7) + ((lane >> 4) & 1) * 8;
    int bkof = ((lane >> 3) & 1) * 8;
    unsigned sA = smem_u32(As), sB = smem_u32(Bs);
    int nch = K >> 6;
    for (int kc = 0; kc < nch; kc++) {
#pragma unroll
        for (int it = 0; it < 4; it++) {
            int lin = tid + it * 256, r = lin >> 3, c = lin & 7;
            *(int4*)(As + r * 72 + c * 8) =
                *(const int4*)(A + (size_t)(m0 + r) * lda + kc * 64 + c * 8);
        }
#pragma unroll
        for (int it = 0; it < 2; it++) {
            int lin = tid + it * 256, r = lin >> 3, c = lin & 7;
            *(int4*)(Bs + r * 72 + c * 8) =
                *(const int4*)(W + (size_t)(n0 + r) * ldw + kc * 64 + c * 8);
        }
        __syncthreads();
#pragma unroll
        for (int ks = 0; ks < 4; ks++) {
            unsigned a[4];
            ldmx4(sA + (unsigned)((arow * 72 + ks * 16 + akof) * 2), a[0], a[1], a[2], a[3]);
#pragma unroll
            for (int q = 0; q < 4; q++) {
                unsigned r0, r1, r2, r3;
                ldmx4(sB + (unsigned)(((q * 16 + brow) * 72 + ks * 16 + bkof) * 2),
                      r0, r1, r2, r3);
                unsigned bb0[2] = {r0, r1}, bb1[2] = {r2, r3};
                mma16816(d[q * 2], a, bb0);
                mma16816(d[q * 2 + 1], a, bb1);
            }
        }
        __syncthreads();
    }
    int g = lane >> 2, t4 = lane & 3;
#pragma unroll
    for (int p = 0; p < 8; p++) {
#pragma unroll
        for (int k = 0; k < 4; k++) {
            int m = m0 + w * 16 + g + (k >> 1) * 8;
            int n = n0 + p * 8 + t4 * 2 + (k & 1);
            float v = d[p][k];
            if (b1) v += b1[n];
            if (b2) v += b2[n];
            if (cmode == 0) C[(size_t)m * ldc + n] = v;
            else if (cmode == 1) {
                int t = m >> 7, b = m & 127;
                C[((size_t)b * TT + t) * VV + n] = v;
            } else {
                int b = m >> 8, s = m & 255;
                Ch[((size_t)b * HH + n) * SS + s] = __float2half(v);
            }
        }
    }
}

// ---------------- persistent encoder layer (mma, both dirs) ----------------
// 128 blocks: dir=bx>>6, h0=(bx&63)*8, N=32 remapped gate cols, M=128, K=512.
__global__ __launch_bounds__(256) void enc_layer_mma(
    const __half* __restrict__ Wr, const float* __restrict__ xproj,
    float* __restrict__ c_buf, __half* __restrict__ hping,
    __half* __restrict__ yout, int ymode)
{
    extern __shared__ __align__(16) unsigned char esm[];
    __half* Ws = (__half*)esm;          // 32 x 520
    __half* Ash = Ws + 32 * 520;        // 128 x 72
    int bx = blockIdx.x, tid = threadIdx.x, lane = tid & 31, w = tid >> 5;
    int dir = bx >> 6, h0 = (bx & 63) * 8;
    const __half* wsrc = Wr + ((size_t)dir * 2048 + (size_t)(bx & 63) * 32) * 512;
#pragma unroll
    for (int it = 0; it < 8; it++) {
        int lin = tid + it * 256, r = lin >> 6, c = lin & 63;
        *(int4*)(Ws + r * 520 + c * 8) = *(const int4*)(wsrc + (size_t)r * 512 + c * 8);
    }
    __syncthreads();
    int arow = w * 16 + (lane & 7) + ((lane >> 3) & 1) * 8;
    int akof = (lane >> 4) * 8;
    int brow = (lane & 7) + ((lane >> 4) & 1) * 8;
    int bkof = ((lane >> 3) & 1) * 8;
    unsigned sW = smem_u32(Ws), sA = smem_u32(Ash);
    int g = lane >> 2, t4 = lane & 3;
    int cur = 0;
    for (int step = 0; step < SS; step++) {
        int t = dir ? (SS - 1 - step) : step;
        const __half* hsrc = hping + (size_t)cur * 131072 + dir * 65536;
        float d[4][4];
#pragma unroll
        for (int q = 0; q < 4; q++)
#pragma unroll
            for (int k = 0; k < 4; k++) d[q][k] = 0.f;
        for (int kc = 0; kc < 8; kc++) {
#pragma unroll
            for (int it = 0; it < 4; it++) {
                int lin = tid + it * 256, r = lin >> 3, c = lin & 7;
                *(int4*)(Ash + r * 72 + c * 8) =
                    *(const int4*)(hsrc + (size_t)r * 512 + kc * 64 + c * 8);
            }
            __syncthreads();
#pragma unroll
            for (int ks = 0; ks < 4; ks++) {
                unsigned a[4];
                ldmx4(sA + (unsigned)((arow * 72 + ks * 16 + akof) * 2),
                      a[0], a[1], a[2], a[3]);
#pragma unroll
                for (int q = 0; q < 2; q++) {
                    unsigned r0, r1, r2, r3;
                    ldmx4(sW + (unsigned)(((q * 16 + brow) * 520 + kc * 64 + ks * 16 + bkof) * 2),
                          r0, r1, r2, r3);
                    unsigned bb0[2] = {r0, r1}, bb1[2] = {r2, r3};
                    mma16816(d[q * 2], a, bb0);
                    mma16816(d[q * 2 + 1], a, bb1);
                }
            }
            __syncthreads();
        }
        __half* hdst = hping + (size_t)(cur ^ 1) * 131072 + dir * 65536;
#pragma unroll
        for (int rr = 0; rr < 2; rr++) {
            int b = w * 16 + g + rr * 8;
            const float* xp = xproj + (((size_t)dir * SS + t) * BB + b) * H4;
#pragma unroll
            for (int hs = 0; hs < 2; hs++) {
                int h = h0 + hs * 4 + t4;
                float gi = d[hs][rr * 2] + xp[h];
                float gf = d[hs][rr * 2 + 1] + xp[512 + h];
                float gg = d[2 + hs][rr * 2] + xp[1024 + h];
                float go = d[2 + hs][rr * 2 + 1] + xp[1536 + h];
                float ig = 1.f / (1.f + expf(-gi));
                float fg = 1.f / (1.f + expf(-gf));
                float gv = tanhf(gg);
                float og = 1.f / (1.f + expf(-go));
                int ci = dir * 65536 + b * 512 + h;
                float c = fg * c_buf[ci] + ig * gv;
                c_buf[ci] = c;
                float hv = og * tanhf(c);
                hdst[b * 512 + h] = __float2half(hv);
                if (ymode == 0)
                    yout[((size_t)t * BB + b) * H2 + dir * HH + h] = __float2half(hv);
                else
                    yout[((size_t)b * SS + t) * H2 + dir * HH + h] = __float2half(hv);
            }
        }
        grid_barrier(NBLK);
        cur ^= 1;
    }
}

// ---------------- decoder cell mma core ----------------
__device__ __forceinline__ void cell_mma(
    __half* Ash, unsigned sA, unsigned sW, int wpitch,
    const __half* A0, int ld0, int nc0, const __half* A1, int ld1, int nc1,
    int tid, int lane, int w, float* d0, float* d1)
{
    int arow = w * 16 + (lane & 7) + ((lane >> 3) & 1) * 8;
    int akof = (lane >> 4) * 8;
    int brow = (lane & 7) + ((lane >> 4) & 1) * 8;
    int bkof = ((lane >> 3) & 1) * 8;
    int nch = nc0 + nc1;
    for (int kc = 0; kc < nch; kc++) {
        const __half* src = (kc < nc0) ? (A0 + kc * 64) : (A1 + (kc - nc0) * 64);
        int ld = (kc < nc0) ? ld0 : ld1;
#pragma unroll
        for (int it = 0; it < 4; it++) {
            int lin = tid + it * 256, r = lin >> 3, c = lin & 7;
            *(int4*)(Ash + r * 72 + c * 8) = *(const int4*)(src + (size_t)r * ld + c * 8);
        }
        __syncthreads();
#pragma unroll
        for (int ks = 0; ks < 4; ks++) {
            unsigned a[4];
            ldmx4(sA + (unsigned)((arow * 72 + ks * 16 + akof) * 2), a[0], a[1], a[2], a[3]);
            unsigned r0, r1, r2, r3;
            ldmx4(sW + (unsigned)((brow * wpitch + kc * 64 + ks * 16 + bkof) * 2),
                  r0, r1, r2, r3);
            unsigned bb0[2] = {r0, r1}, bb1[2] = {r2, r3};
            mma16816(d0, a, bb0);
            mma16816(d1, a, bb1);
        }
        __syncthreads();
    }
}

// ---------------- persistent decoder ----------------
__global__ __launch_bounds__(256) void decoder_mma(
    const __half* __restrict__ encP, const __half* __restrict__ enc16,
    const float* __restrict__ sbias, const int* __restrict__ source,
    const float* __restrict__ eproj,
    const __half* __restrict__ Wc0, const __half* __restrict__ Wc1,
    const float* __restrict__ dbih1, const float* __restrict__ dbhh1,
    __half* __restrict__ d0h, float* __restrict__ d0c,
    __half* __restrict__ d1h, float* __restrict__ d1c,
    __half* __restrict__ ctx16, __half* __restrict__ d1a16)
{
    extern __shared__ __align__(16) unsigned char dsm[];
    __half* W0s = (__half*)dsm;              // 16 x 1544
    __half* W1s = W0s + 16 * 1544;           // 16 x 1032
    __half* Ash = W1s + 16 * 1032;           // 128 x 72
    float* shd = (float*)(Ash + 128 * 72);   // 512
    float* sred = shd + 512;                 // 256
    float* satt = sred + 256;                // 256

    int bx = blockIdx.x, tid = threadIdx.x, lane = tid & 31, w = tid >> 5;
    for (int it = 0; it < 12; it++) {
        int lin = tid + it * 256;
        int r = lin / 192, c = lin % 192;
        *(int4*)(W0s + r * 1544 + c * 8) =
            *(const int4*)(Wc0 + ((size_t)(bx * 16 + r)) * 1536 + c * 8);
    }
#pragma unroll
    for (int it = 0; it < 8; it++) {
        int lin = tid + it * 256, r = lin >> 7, c = lin & 127;
        *(int4*)(W1s + r * 1032 + c * 8) =
            *(const int4*)(Wc1 + ((size_t)(bx * 16 + r)) * 1024 + c * 8);
    }
    int g = lane >> 2, t4 = lane & 3;
    int hcell = bx * 4 + t4;
    float bi1 = dbih1[hcell] + dbhh1[hcell];
    float bf1 = dbih1[512 + hcell] + dbhh1[512 + hcell];
    float bg1 = dbih1[1024 + hcell] + dbhh1[1024 + hcell];
    float bo1 = dbih1[1536 + hcell] + dbhh1[1536 + hcell];
    __syncthreads();
    unsigned sW0 = smem_u32(W0s), sW1 = smem_u32(W1s), sA = smem_u32(Ash);

    for (int t = 0; t < TT; t++) {
        int cur = t & 1;
        const __half* d0cur = d0h + (size_t)cur * 65536;
        __half* d0nxt = d0h + (size_t)(cur ^ 1) * 65536;
        const __half* d1cur = d1h + (size_t)cur * 65536;
        __half* d1nxt = d1h + (size_t)(cur ^ 1) * 65536;

        // phase 1: attention (block = batch bx)
        {
            int b = bx;
            shd[tid] = __half2float(d1cur[b * 512 + tid]);
            shd[256 + tid] = __half2float(d1cur[b * 512 + 256 + tid]);
            __syncthreads();
            float sc = sbias[b * SS + tid];
            const __half* ep = encP + (size_t)b * HH * SS + tid;
#pragma unroll 8
            for (int h = 0; h < HH; h++) sc += __half2float(ep[(size_t)h * SS]) * shd[h];
            if (source[b * SS + tid] == 0) sc = -1e9f;
            sred[tid] = sc;
            __syncthreads();
            for (int o = 128; o; o >>= 1) {
                if (tid < o) sred[tid] = fmaxf(sred[tid], sred[tid + o]);
                __syncthreads();
            }
            float mx = sred[0];
            __syncthreads();
            float e = expf(sc - mx);
            sred[tid] = e;
            __syncthreads();
            for (int o = 128; o; o >>= 1) {
                if (tid < o) sred[tid] += sred[tid + o];
                __syncthreads();
            }
            satt[tid] = e / sred[0];
            __syncthreads();
            float a0x = 0, a0y = 0, a1x = 0, a1y = 0;
            const __half2* e2 = (const __half2*)(enc16 + (size_t)b * SS * H2);
            for (int s = 0; s < SS; s++) {
                float a = satt[s];
                float2 f0 = __half22float2(e2[(size_t)s * 512 + tid]);
                float2 f1 = __half22float2(e2[(size_t)s * 512 + 256 + tid]);
                a0x += a * f0.x; a0y += a * f0.y;
                a1x += a * f1.x; a1y += a * f1.y;
            }
            __half2* cp = (__half2*)(ctx16 + (size_t)b * H2);
            cp[tid] = __floats2half2_rn(a0x, a0y);
            cp[256 + tid] = __floats2half2_rn(a1x, a1y);
        }
        grid_barrier(NBLK);

        // phase 2: cell0 (A = [ctx | d0h], W resident)
        {
            float d0[4] = {0, 0, 0, 0}, d1[4] = {0, 0, 0, 0};
            cell_mma(Ash, sA, sW0, 1544, ctx16, H2, 16, d0cur, HH, 8,
                     tid, lane, w, d0, d1);
            const float* ep = eproj + ((size_t)t * BB) * H4;
#pragma unroll
            for (int rr = 0; rr < 2; rr++) {
                int b = w * 16 + g + rr * 8;
                const float* xp = ep + (size_t)b * H4;
                float gi = d0[rr * 2] + xp[hcell];
                float gf = d0[rr * 2 + 1] + xp[512 + hcell];
                float gg = d1[rr * 2] + xp[1024 + hcell];
                float go = d1[rr * 2 + 1] + xp[1536 + hcell];
                float ig = 1.f / (1.f + expf(-gi));
                float fg = 1.f / (1.f + expf(-gf));
                float gv = tanhf(gg);
                float og = 1.f / (1.f + expf(-go));
                int idx = b * 512 + hcell;
                float c = fg * d0c[idx] + ig * gv;
                d0c[idx] = c;
                d0nxt[idx] = __float2half(og * tanhf(c));
            }
        }
        grid_barrier(NBLK);

        // phase 3: cell1 (A = [d0h_new | d1h])
        {
            float d0[4] = {0, 0, 0, 0}, d1[4] = {0, 0, 0, 0};
            cell_mma(Ash, sA, sW1, 1032, d0nxt, HH, 8, d1cur, HH, 8,
                     tid, lane, w, d0, d1);
#pragma unroll
            for (int rr = 0; rr < 2; rr++) {
                int b = w * 16 + g + rr * 8;
                float gi = d0[rr * 2] + bi1;
                float gf = d0[rr * 2 + 1] + bf1;
                float gg = d1[rr * 2] + bg1;
                float go = d1[rr * 2 + 1] + bo1;
                float ig = 1.f / (1.f + expf(-gi));
                float fg = 1.f / (1.f + expf(-gf));
                float gv = tanhf(gg);
                float og = 1.f / (1.f + expf(-go));
                int idx = b * 512 + hcell;
                float c = fg * d1c[idx] + ig * gv;
                d1c[idx] = c;
                float hv = og * tanhf(c);
                d1nxt[idx] = __float2half(hv);
                d1a16[((size_t)t * BB + b) * HH + hcell] = __float2half(hv);
            }
        }
        grid_barrier(NBLK);
    }
}

// =======================================================================
extern "C" void kernel_launch(void* const* d_in, const int* in_sizes, int n_in,
                              void* d_out, int out_size)
{
    const int* source = (const int*)d_in[0];
    const int* dec_in = (const int*)d_in[1];
    const float* emb = (const float*)d_in[2];
    const float* eWih0 = (const float*)d_in[3];
    const float* eWhh0 = (const float*)d_in[4];
    const float* ebih0 = (const float*)d_in[5];
    const float* ebhh0 = (const float*)d_in[6];
    const float* eWih1 = (const float*)d_in[7];
    const float* eWhh1 = (const float*)d_in[8];
    const float* ebih1 = (const float*)d_in[9];
    const float* ebhh1 = (const float*)d_in[10];
    const float* dWih0 = (const float*)d_in[11];
    const float* dWhh0 = (const float*)d_in[12];
    const float* dbih0 = (const float*)d_in[13];
    const float* dbhh0 = (const float*)d_in[14];
    const float* dWih1 = (const float*)d_in[15];
    const float* dWhh1 = (const float*)d_in[16];
    const float* dbih1 = (const float*)d_in[17];
    const float* dbhh1 = (const float*)d_in[18];
    const float* Wq = (const float*)d_in[19];
    const float* bq = (const float*)d_in[20];
    const float* Wout = (const float*)d_in[21];
    const float* bout = (const float*)d_in[22];
    float* out = (float*)d_out;

    __half *p_xs16, *p_dece16, *p_y016, *p_enc16, *p_encP, *p_d1a16;
    __half *p_ewih0, *p_ewih1, *p_ewhh0r, *p_ewhh1r, *p_dwihA, *p_wc0, *p_wc1, *p_wqT16, *p_wout16;
    __half *p_eh0p, *p_eh1p, *p_d0h, *p_d1h, *p_ctx16;
    float *p_xproj, *p_sbias, *p_eproj, *p_ec0, *p_ec1, *p_d0c, *p_d1c;
    cudaGetSymbolAddress((void**)&p_xs16, g_xs16);
    cudaGetSymbolAddress((void**)&p_dece16, g_dece16);
    cudaGetSymbolAddress((void**)&p_xproj, g_xproj);
    cudaGetSymbolAddress((void**)&p_y016, g_y016);
    cudaGetSymbolAddress((void**)&p_enc16, g_enc16);
    cudaGetSymbolAddress((void**)&p_encP, g_encP);
    cudaGetSymbolAddress((void**)&p_sbias, g_sbias);
    cudaGetSymbolAddress((void**)&p_eproj, g_eproj);
    cudaGetSymbolAddress((void**)&p_d1a16, g_d1a16);
    cudaGetSymbolAddress((void**)&p_ewih0, g_ewih0);
    cudaGetSymbolAddress((void**)&p_ewih1, g_ewih1);
    cudaGetSymbolAddress((void**)&p_ewhh0r, g_ewhh0r);
    cudaGetSymbolAddress((void**)&p_ewhh1r, g_ewhh1r);
    cudaGetSymbolAddress((void**)&p_dwihA, g_dwihA);
    cudaGetSymbolAddress((void**)&p_wc0, g_wc0);
    cudaGetSymbolAddress((void**)&p_wc1, g_wc1);
    cudaGetSymbolAddress((void**)&p_wqT16, g_wqT16);
    cudaGetSymbolAddress((void**)&p_wout16, g_wout16);
    cudaGetSymbolAddress((void**)&p_eh0p, g_eh0p);
    cudaGetSymbolAddress((void**)&p_ec0, g_ec0);
    cudaGetSymbolAddress((void**)&p_eh1p, g_eh1p);
    cudaGetSymbolAddress((void**)&p_ec1, g_ec1);
    cudaGetSymbolAddress((void**)&p_d0h, g_d0h);
    cudaGetSymbolAddress((void**)&p_d0c, g_d0c);
    cudaGetSymbolAddress((void**)&p_d1h, g_d1h);
    cudaGetSymbolAddress((void**)&p_d1c, g_d1c);
    cudaGetSymbolAddress((void**)&p_ctx16, g_ctx16);

    cudaFuncSetAttribute(enc_layer_mma, cudaFuncAttributeMaxDynamicSharedMemorySize, 51712);
    cudaFuncSetAttribute(decoder_mma, cudaFuncAttributeMaxDynamicSharedMemorySize, 104960);

    // zero encoder states (both ping slots + c)
    cudaMemsetAsync(p_eh0p, 0, 2 * 2 * BB * HH * sizeof(__half));
    cudaMemsetAsync(p_ec0, 0, 2 * BB * HH * sizeof(float));
    cudaMemsetAsync(p_eh1p, 0, 2 * 2 * BB * HH * sizeof(__half));
    cudaMemsetAsync(p_ec1, 0, 2 * BB * HH * sizeof(float));

    // gathers + weight conversions
    {
        long total = (long)SS * BB * EE;
        gather16_kernel<<<(unsigned)((total + 255) / 256), 256>>>(source, emb, p_xs16, SS);
        gather16_kernel<<<(unsigned)((total + 255) / 256), 256>>>(dec_in, emb, p_dece16, TT);
        cvt_plain<<<(2 * H4 * EE) / 256, 256>>>(eWih0, p_ewih0, 2 * H4 * EE);
        cvt_plain<<<(2 * H4 * H2) / 256, 256>>>(eWih1, p_ewih1, 2 * H4 * H2);
        cvt_plain<<<(VV * HH) / 256, 256>>>(Wout, p_wout16, VV * HH);
        cvt_slice<<<(H4 * EE) / 256, 256>>>(dWih0, EE + H2, p_dwihA, EE, H4 * EE);
        cvt_wq<<<(HH * H2) / 256, 256>>>(Wq, p_wqT16);
        cvt_enc_whh<<<(2 * H4 * HH) / 256, 256>>>(eWhh0, p_ewhh0r);
        cvt_enc_whh<<<(2 * H4 * HH) / 256, 256>>>(eWhh1, p_ewhh1r);
        cvt_dec_w0<<<(H4 * 1536) / 256, 256>>>(dWih0, dWhh0, p_wc0);
        cvt_dec_w1<<<(H4 * H2) / 256, 256>>>(dWih1, dWhh1, p_wc1);
    }

    const size_t slab = (size_t)SS * BB * H4;

    // encoder layer 0
    for (int d = 0; d < 2; d++)
        gemm16_kernel<<<dim3(256, 32), 256>>>(
            p_xs16, EE, p_ewih0 + (size_t)d * H4 * EE, EE,
            ebih0 + (size_t)d * H4, ebhh0 + (size_t)d * H4,
            p_xproj + d * slab, H4, nullptr, EE, 0);
    enc_layer_mma<<<NBLK, 256, 51712>>>(p_ewhh0r, p_xproj, p_ec0, p_eh0p, p_y016, 0);

    // encoder layer 1
    for (int d = 0; d < 2; d++)
        gemm16_kernel<<<dim3(256, 32), 256>>>(
            p_y016, H2, p_ewih1 + (size_t)d * H4 * H2, H2,
            ebih1 + (size_t)d * H4, ebhh1 + (size_t)d * H4,
            p_xproj + d * slab, H4, nullptr, H2, 0);
    enc_layer_mma<<<NBLK, 256, 51712>>>(p_ewhh1r, p_xproj, p_ec1, p_eh1p, p_enc16, 1);

    // attention precompute
    gemm16_kernel<<<dim3(256, 8), 256>>>(p_enc16, H2, p_wqT16, H2,
                                         nullptr, nullptr, nullptr, 0, p_encP, H2, 2);
    sbias16_kernel<<<4096, 256>>>(p_enc16, bq, p_sbias);

    // decoder init + e-projection
    init_dec_kernel<<<(BB * HH) / 256, 256>>>(p_eh0p, p_ec0, p_eh1p, p_ec1,
                                              p_d0h, p_d0c, p_d1h, p_d1c);
    gemm16_kernel<<<dim3(256, 32), 256>>>(p_dece16, EE, p_dwihA, EE,
                                          dbih0, dbhh0, p_eproj, H4, nullptr, EE, 0);

    // persistent decoder
    decoder_mma<<<NBLK, 256, 104960>>>(p_encP, p_enc16, p_sbias, source, p_eproj,
                                       p_wc0, p_wc1, dbih1, dbhh1,
                                       p_d0h, p_d0c, p_d1h, p_d1c, p_ctx16, p_d1a16);

    // logits
    gemm16_kernel<<<dim3(256, 8), 256>>>(p_d1a16, HH, p_wout16, HH,
                                         bout, nullptr, out, VV, nullptr, HH, 1);
}